// round 11
// baseline (speedup 1.0000x reference)
#include <cuda_runtime.h>
#include <cuda_bf16.h>

// ANFIS fuzzy inference, batch=2M rows x 4 features. Single kernel.
// out = sum_j(w_j * clip(conseq_j)) / max(sum_j w_j, 1e-8),
// w_j = prod of 4 Gaussian memberships.
//
//  - Per-block constant prep into smem (redundant per block, ~100 cyc):
//      s_ab[i]  = (a', b') with a' = (1/sigma)*sqrt(0.5*log2 e), b' = -c*a'
//      s_cqp[m] = clip(conseq[GRP_CQ[m]],0,100)  — PERMUTED into group
//                 consumption order so the weighted loop reads it as
//                 8 sequential LDS.128.
//  - Constant delivery: 11 LDS.64 + 8 LDS.128 per row (19 issues vs 52
//    scalar) — broadcast, conflict-free.
//  - mu_i = ex2((-d)*d) (negation folded into FMUL source modifier).
//  - pair-product CSE: P[9] = mu[0..2] x mu[3..5], Q[6] = mu[6..8] x mu[9..10].
//  - group factorization over the 6 shared Q factors; split accumulators;
//    CSE'd unweighted group sums.
//  - 2 rows/thread, 256 threads, natural regalloc.

namespace {
// Rules grouped by q = (ante2-6)*2 + (ante3-9); p = ante0*3 + (ante1-3).
// Verified against RULE_ANTECEDENTS.
//   group extents: g0: m 0-6, g1: 7-10, g2: 11-15, g3: 16-20, g4: 21-25, g5: 26-29
__device__ constexpr int GRP_P[30]  = {0,3,1,2,8,5,7,  8,7,5,4,  0,4,3,6,5,
                                       0,1,3,2,8,  0,1,3,2,7,  0,1,3,4};
__device__ constexpr int GRP_CQ[30] = {9,13,15,19,23,27,28,  22,24,25,29,
                                       2,11,17,18,20,  4,10,12,14,26,
                                       0,3,6,7,21,  1,5,8,16};
// m -> group index (from offsets {0,7,11,16,21,26,30})
__device__ constexpr int GRP_OF[30] = {0,0,0,0,0,0,0, 1,1,1,1, 2,2,2,2,2,
                                       3,3,3,3,3, 4,4,4,4,4, 5,5,5,5};
__device__ constexpr int DM[11] = {0,0,0,1,1,1,2,2,2,3,3};
}

__device__ __forceinline__ float ex2(float t) {
    float r; asm("ex2.approx.ftz.f32 %0, %1;" : "=f"(r) : "f"(t)); return r;
}

constexpr int THREADS = 256;
constexpr int ROWS_PER_THREAD = 2;
constexpr int TILE = THREADS * ROWS_PER_THREAD;   // 512 rows/block

struct Smem {
    float2 ab[11];                     // (a', b') pairs -> LDS.64
    __align__(16) float cqp[32];       // permuted cq (+2 pad) -> LDS.128 x8
};

__device__ __forceinline__ float anfis_row(const float4 xv, const Smem& sm)
{
    const float xd[4] = {xv.x, xv.y, xv.z, xv.w};

    // 11 memberships: LDS.64 + FFMA + FMUL(neg-src) + MUFU each.
    float mu[11];
    #pragma unroll
    for (int i = 0; i < 11; i++) {
        float2 ab = sm.ab[i];
        float d = fmaf(xd[DM[i]], ab.x, ab.y);
        mu[i] = ex2(-d * d);
    }

    // Pair products.
    float Pv[9], Qv[6];
    #pragma unroll
    for (int i = 0; i < 3; i++)
        #pragma unroll
        for (int j = 0; j < 3; j++)
            Pv[i * 3 + j] = mu[i] * mu[3 + j];
    #pragma unroll
    for (int i = 0; i < 3; i++)
        #pragma unroll
        for (int j = 0; j < 2; j++)
            Qv[i * 2 + j] = mu[6 + i] * mu[9 + j];

    // Weighted group inner sums: cq streamed as 8 LDS.128 in permuted order.
    float s1[6];
    #pragma unroll
    for (int g = 0; g < 6; g++) s1[g] = 0.0f;

    const float4* cq4 = (const float4*)sm.cqp;
    #pragma unroll
    for (int chunk = 0; chunk < 8; chunk++) {
        float4 C = cq4[chunk];
        const float cv[4] = {C.x, C.y, C.z, C.w};
        #pragma unroll
        for (int e = 0; e < 4; e++) {
            const int m = chunk * 4 + e;
            if (m < 30) {
                s1[GRP_OF[m]] = fmaf(Pv[GRP_P[m]], cv[e], s1[GRP_OF[m]]);
            }
        }
    }

    // Unweighted group sums with CSE (16 ADDs).
    float u = (Pv[0] + Pv[1]) + Pv[3];   // {0,1,3}
    float v = u + Pv[2];                 // {0,1,2,3}
    float s0_0 = v + ((Pv[8] + Pv[5]) + Pv[7]);
    float s0_1 = (Pv[8] + Pv[7]) + (Pv[5] + Pv[4]);
    float s0_2 = ((Pv[0] + Pv[4]) + (Pv[3] + Pv[6])) + Pv[5];
    float s0_3 = v + Pv[8];
    float s0_4 = v + Pv[7];
    float s0_5 = u + Pv[4];

    // Split accumulators: two independent 3-op chains each.
    float accA = Qv[0] * s1[0];
    float accB = Qv[1] * s1[1];
    accA = fmaf(Qv[2], s1[2], accA);
    accB = fmaf(Qv[3], s1[3], accB);
    accA = fmaf(Qv[4], s1[4], accA);
    accB = fmaf(Qv[5], s1[5], accB);

    float wsA = Qv[0] * s0_0;
    float wsB = Qv[1] * s0_1;
    wsA = fmaf(Qv[2], s0_2, wsA);
    wsB = fmaf(Qv[3], s0_3, wsB);
    wsA = fmaf(Qv[4], s0_4, wsA);
    wsB = fmaf(Qv[5], s0_5, wsB);

    return __fdividef(accA + accB, fmaxf(wsA + wsB, 1e-8f));
}

__global__ void __launch_bounds__(THREADS)
anfis_kernel(const float4* __restrict__ x,
             const float*  __restrict__ c,
             const float*  __restrict__ log_s,
             const float*  __restrict__ conseq,
             float* __restrict__ out,
             int n)
{
    __shared__ Smem sm;

    const int t = threadIdx.x;
    if (t < 11) {
        const float KS = 0.8493218002880191f;  // sqrt(0.5 * log2(e))
        float ci  = __ldg(c + t);
        float sg  = fmaxf(__expf(__ldg(log_s + t)), 0.001f);
        float ap  = KS / sg;
        sm.ab[t] = make_float2(ap, -ci * ap);
    }
    if (t < 32) {
        // Permuted clipped conseq; pad [30..31] with 0.
        float v = 0.0f;
        if (t < 30) v = fminf(fmaxf(__ldg(conseq + GRP_CQ[t]), 0.0f), 100.0f);
        sm.cqp[t] = v;
    }
    __syncthreads();

    const int base = blockIdx.x * TILE + t;

    if (blockIdx.x * TILE + TILE <= n) {
        // Full tile: 2 unconditional coalesced LDG.128.
        float4 xv0 = __ldg(x + base);
        float4 xv1 = __ldg(x + base + THREADS);

        float r0 = anfis_row(xv0, sm);
        float r1 = anfis_row(xv1, sm);

        out[base]           = r0;
        out[base + THREADS] = r1;
    } else {
        // Tail: predicated.
        #pragma unroll
        for (int k = 0; k < ROWS_PER_THREAD; k++) {
            int r = base + k * THREADS;
            if (r < n) {
                float4 xv = __ldg(x + r);
                out[r] = anfis_row(xv, sm);
            }
        }
    }
}

extern "C" void kernel_launch(void* const* d_in, const int* in_sizes, int n_in,
                              void* d_out, int out_size)
{
    const float* x      = (const float*)d_in[0];
    const float* c      = (const float*)d_in[1];
    const float* log_s  = (const float*)d_in[2];
    const float* conseq = (const float*)d_in[3];
    float* out          = (float*)d_out;

    int n = in_sizes[0] / 4;   // rows
    int blocks = (n + TILE - 1) / TILE;

    anfis_kernel<<<blocks, THREADS>>>((const float4*)x, c, log_s, conseq, out, n);
}

// round 12
// speedup vs baseline: 1.1324x; 1.1324x over previous
#include <cuda_runtime.h>
#include <cuda_bf16.h>

// ANFIS fuzzy inference, batch=2M rows x 4 features.
// out = sum_j(w_j * clip(conseq_j)) / max(sum_j w_j, 1e-8),
// w_j = prod of 4 Gaussian memberships.
//
// Two graph nodes with PDL overlap (R10 structure):
//  1) prep kernel computes a' = (1/sigma)*sqrt(0.5*log2 e), b' = -c*a',
//     cq = clip(conseq,0,100) directly into the __constant__ backing store
//     in VECTOR-FRIENDLY layout, then triggers programmatic launch completion:
//       - ab[11]  : interleaved (a',b') float2 -> one LDC.64 per membership
//       - cqp[32] : cq PERMUTED into group consumption order, 16B-aligned
//                   -> 8 x LDC.128 in the weighted loop
//  2) main kernel (ProgrammaticStreamSerialization): prefetches its x rows,
//     griddepsync, then evaluates. Constants from the constant bank --
//     zero GPR cost, vector LDC delivery.
//
// Row math (validated):
//  - mu_i = ex2((-d)*d), d = x*a'+b' (negation folded into FMUL operand).
//  - pair-product CSE: P[9] = mu[0..2] x mu[3..5], Q[6] = mu[6..8] x mu[9..10].
//  - group factorization over the 6 shared Q factors; split accumulators;
//    CSE'd unweighted group sums.
//  - 2 rows/thread, 256 threads.

namespace {
// Rules grouped by q = (ante2-6)*2 + (ante3-9); p = ante0*3 + (ante1-3).
// Verified against RULE_ANTECEDENTS.
//   group extents: g0: m 0-6, g1: 7-10, g2: 11-15, g3: 16-20, g4: 21-25, g5: 26-29
__device__ constexpr int GRP_P[30]  = {0,3,1,2,8,5,7,  8,7,5,4,  0,4,3,6,5,
                                       0,1,3,2,8,  0,1,3,2,7,  0,1,3,4};
__device__ constexpr int GRP_CQ[30] = {9,13,15,19,23,27,28,  22,24,25,29,
                                       2,11,17,18,20,  4,10,12,14,26,
                                       0,3,6,7,21,  1,5,8,16};
// m -> group index (from offsets {0,7,11,16,21,26,30})
__device__ constexpr int GRP_OF[30] = {0,0,0,0,0,0,0, 1,1,1,1, 2,2,2,2,2,
                                       3,3,3,3,3, 4,4,4,4,4, 5,5,5,5};
__device__ constexpr int DM[11] = {0,0,0,1,1,1,2,2,2,3,3};
}

// Constant blob: cqp first (16B aligned at symbol start), then ab pairs.
struct CstBlob {
    float  cqp[32];    // permuted clipped conseq, padded; read as float4 x8
    float2 ab[11];     // (a', b') interleaved; read as LDC.64
};
__constant__ CstBlob g_cst;

__device__ __forceinline__ float ex2(float t) {
    float r; asm("ex2.approx.ftz.f32 %0, %1;" : "=f"(r) : "f"(t)); return r;
}

// Writes the __constant__ backing store directly, then signals that the
// dependent grid may launch.
__global__ void prep_kernel(const float* __restrict__ c,
                            const float* __restrict__ log_s,
                            const float* __restrict__ conseq,
                            CstBlob* __restrict__ cst)
{
    const int t = threadIdx.x;
    if (t < 11) {
        const float KS = 0.8493218002880191f;  // sqrt(0.5 * log2(e))
        float ci  = c[t];
        float sg  = fmaxf(__expf(log_s[t]), 0.001f);
        float ap  = KS / sg;
        cst->ab[t] = make_float2(ap, -ci * ap);
    }
    if (t < 32) {
        float v = 0.0f;
        if (t < 30) v = fminf(fmaxf(conseq[GRP_CQ[t]], 0.0f), 100.0f);
        cst->cqp[t] = v;
    }
    __threadfence();   // order stores to L2 before the trigger
#if __CUDA_ARCH__ >= 900
    cudaTriggerProgrammaticLaunchCompletion();
#endif
}

constexpr int THREADS = 256;
constexpr int ROWS_PER_THREAD = 2;
constexpr int TILE = THREADS * ROWS_PER_THREAD;   // 512 rows/block

__device__ __forceinline__ float anfis_row(const float4 xv)
{
    const float xd[4] = {xv.x, xv.y, xv.z, xv.w};

    // 11 memberships: LDC.64 + FFMA + FMUL(neg-src) + MUFU each.
    float mu[11];
    #pragma unroll
    for (int i = 0; i < 11; i++) {
        float2 ab = g_cst.ab[i];
        float d = fmaf(xd[DM[i]], ab.x, ab.y);
        mu[i] = ex2(-d * d);
    }

    // Pair products.
    float Pv[9], Qv[6];
    #pragma unroll
    for (int i = 0; i < 3; i++)
        #pragma unroll
        for (int j = 0; j < 3; j++)
            Pv[i * 3 + j] = mu[i] * mu[3 + j];
    #pragma unroll
    for (int i = 0; i < 3; i++)
        #pragma unroll
        for (int j = 0; j < 2; j++)
            Qv[i * 2 + j] = mu[6 + i] * mu[9 + j];

    // Weighted group inner sums: cq streamed as 8 LDC.128 in permuted order.
    float s1[6];
    #pragma unroll
    for (int g = 0; g < 6; g++) s1[g] = 0.0f;

    const float4* cq4 = (const float4*)g_cst.cqp;
    #pragma unroll
    for (int chunk = 0; chunk < 8; chunk++) {
        float4 C = cq4[chunk];
        const float cv[4] = {C.x, C.y, C.z, C.w};
        #pragma unroll
        for (int e = 0; e < 4; e++) {
            const int m = chunk * 4 + e;
            if (m < 30) {
                s1[GRP_OF[m]] = fmaf(Pv[GRP_P[m]], cv[e], s1[GRP_OF[m]]);
            }
        }
    }

    // Unweighted group sums with CSE (16 ADDs).
    float u = (Pv[0] + Pv[1]) + Pv[3];   // {0,1,3}
    float v = u + Pv[2];                 // {0,1,2,3}
    float s0_0 = v + ((Pv[8] + Pv[5]) + Pv[7]);
    float s0_1 = (Pv[8] + Pv[7]) + (Pv[5] + Pv[4]);
    float s0_2 = ((Pv[0] + Pv[4]) + (Pv[3] + Pv[6])) + Pv[5];
    float s0_3 = v + Pv[8];
    float s0_4 = v + Pv[7];
    float s0_5 = u + Pv[4];

    // Split accumulators: two independent 3-op chains each.
    float accA = Qv[0] * s1[0];
    float accB = Qv[1] * s1[1];
    accA = fmaf(Qv[2], s1[2], accA);
    accB = fmaf(Qv[3], s1[3], accB);
    accA = fmaf(Qv[4], s1[4], accA);
    accB = fmaf(Qv[5], s1[5], accB);

    float wsA = Qv[0] * s0_0;
    float wsB = Qv[1] * s0_1;
    wsA = fmaf(Qv[2], s0_2, wsA);
    wsB = fmaf(Qv[3], s0_3, wsB);
    wsA = fmaf(Qv[4], s0_4, wsA);
    wsB = fmaf(Qv[5], s0_5, wsB);

    return __fdividef(accA + accB, fmaxf(wsA + wsB, 1e-8f));
}

__global__ void __launch_bounds__(THREADS)
anfis_kernel(const float4* __restrict__ x,
             float* __restrict__ out,
             int n)
{
    const int base = blockIdx.x * TILE + threadIdx.x;
    const bool full = (blockIdx.x * TILE + TILE <= n);

    if (full) {
        // Issue the x loads BEFORE the dependency sync — independent of prep.
        float4 xv0 = __ldg(x + base);
        float4 xv1 = __ldg(x + base + THREADS);

#if __CUDA_ARCH__ >= 900
        cudaGridDependencySynchronize();
#endif

        float r0 = anfis_row(xv0);
        float r1 = anfis_row(xv1);

        out[base]           = r0;
        out[base + THREADS] = r1;
    } else {
#if __CUDA_ARCH__ >= 900
        cudaGridDependencySynchronize();
#endif
        #pragma unroll
        for (int k = 0; k < ROWS_PER_THREAD; k++) {
            int r = base + k * THREADS;
            if (r < n) {
                float4 xv = __ldg(x + r);
                out[r] = anfis_row(xv);
            }
        }
    }
}

extern "C" void kernel_launch(void* const* d_in, const int* in_sizes, int n_in,
                              void* d_out, int out_size)
{
    const float* x      = (const float*)d_in[0];
    const float* c      = (const float*)d_in[1];
    const float* log_s  = (const float*)d_in[2];
    const float* conseq = (const float*)d_in[3];
    float* out          = (float*)d_out;

    int n = in_sizes[0] / 4;   // rows
    int blocks = (n + TILE - 1) / TILE;

    // Device address of the __constant__ symbol (host API, capture-legal).
    void* cst_ptr = nullptr;
    cudaGetSymbolAddress(&cst_ptr, g_cst);

    // Node 1: prep (triggers programmatic launch completion early).
    prep_kernel<<<1, 32>>>(c, log_s, conseq, (CstBlob*)cst_ptr);

    // Node 2: main kernel with programmatic dependent launch.
    cudaLaunchConfig_t cfg = {};
    cfg.gridDim  = dim3((unsigned)blocks, 1, 1);
    cfg.blockDim = dim3(THREADS, 1, 1);
    cfg.dynamicSmemBytes = 0;
    cfg.stream = 0;
    cudaLaunchAttribute attrs[1];
    attrs[0].id = cudaLaunchAttributeProgrammaticStreamSerialization;
    attrs[0].val.programmaticStreamSerializationAllowed = 1;
    cfg.attrs = attrs;
    cfg.numAttrs = 1;

    cudaError_t err = cudaLaunchKernelEx(&cfg, anfis_kernel,
                                         (const float4*)x, out, n);
    if (err != cudaSuccess) {
        // Fallback: plain serialized launch (still correct).
        anfis_kernel<<<blocks, THREADS>>>((const float4*)x, out, n);
    }
}